// round 1
// baseline (speedup 1.0000x reference)
#include <cuda_runtime.h>

#define Bc 8
#define Cc 128
#define Nn 10000
#define Kk 16
#define CO 256
#define NT (Bc*Nn)   // 80000 total columns
#define TN 32        // columns per block

// Scratch: node-major (B,N,C) layouts so neighbor gathers are contiguous 512B columns.
__device__ float g_h[NT*Cc];
__device__ float g_q[NT*Cc];

// ---------------------------------------------------------------------------
// Kernel 1: per 32-column tile, compute h = relu(W1 @ x + b1) and
//           q = relu(Wp @ h + bp). Both stored node-major: buf[(b*N+n)*C + d].
// Block: 256 threads, thread tile 4 rows x 4 cols.
// ---------------------------------------------------------------------------
__global__ __launch_bounds__(256, 2)
void k1(const float* __restrict__ x, const float* __restrict__ W1,
        const float* __restrict__ b1v, const float* __restrict__ Wp,
        const float* __restrict__ bpv)
{
    extern __shared__ float smem[];
    float* Ws = smem;                  // [128][132] transposed weights (pad 132)
    float* Xs = Ws + 128*132;          // [128][32]  K-major input tile
    float* Hs = Xs + 128*32;           // [32][132]  h tile, column-major per node
    float* bs = Hs + 32*132;           // [128] bias
    int* xbase = (int*)(bs + 128);     // [32] per-column x base
    int* obase = xbase + 32;           // [32] per-column output base (col*128)

    const int tid  = threadIdx.x;
    const int col0 = blockIdx.x * TN;

    if (tid < TN) {
        int col = col0 + tid;
        int b = col / Nn;
        int n = col - b * Nn;
        xbase[tid] = b * (Cc * Nn) + n;   // x[b][c][n] = x[xbase + c*Nn]
        obase[tid] = col * Cc;
    }
    // W1 transposed into Ws[c][d]
    for (int i = tid; i < Cc*Cc; i += 256) {
        int d = i >> 7, c = i & 127;
        Ws[c*132 + d] = W1[i];
    }
    if (tid < Cc) bs[tid] = b1v[tid];
    __syncthreads();

    // X tile: Xs[c][j]
    for (int i = tid; i < Cc*TN; i += 256) {
        int c = i >> 5, j = i & 31;
        Xs[c*32 + j] = x[xbase[j] + c * Nn];
    }
    __syncthreads();

    const int d0 = (tid & 31) * 4;   // row group (output channel)
    const int j0 = (tid >> 5) * 4;   // column group

    float acc[4][4];
    #pragma unroll
    for (int i = 0; i < 4; i++)
        #pragma unroll
        for (int j = 0; j < 4; j++) acc[i][j] = 0.f;

    #pragma unroll 4
    for (int k = 0; k < Cc; k++) {
        float4 wv = *(const float4*)(Ws + k*132 + d0);
        float4 xv = *(const float4*)(Xs + k*32  + j0);
        acc[0][0] += wv.x * xv.x; acc[0][1] += wv.x * xv.y;
        acc[0][2] += wv.x * xv.z; acc[0][3] += wv.x * xv.w;
        acc[1][0] += wv.y * xv.x; acc[1][1] += wv.y * xv.y;
        acc[1][2] += wv.y * xv.z; acc[1][3] += wv.y * xv.w;
        acc[2][0] += wv.z * xv.x; acc[2][1] += wv.z * xv.y;
        acc[2][2] += wv.z * xv.z; acc[2][3] += wv.z * xv.w;
        acc[3][0] += wv.w * xv.x; acc[3][1] += wv.w * xv.y;
        acc[3][2] += wv.w * xv.z; acc[3][3] += wv.w * xv.w;
    }

    float bias0 = bs[d0+0], bias1 = bs[d0+1], bias2 = bs[d0+2], bias3 = bs[d0+3];
    #pragma unroll
    for (int jj = 0; jj < 4; jj++) {
        float4 hv;
        hv.x = fmaxf(acc[0][jj] + bias0, 0.f);
        hv.y = fmaxf(acc[1][jj] + bias1, 0.f);
        hv.z = fmaxf(acc[2][jj] + bias2, 0.f);
        hv.w = fmaxf(acc[3][jj] + bias3, 0.f);
        *(float4*)(Hs + (j0+jj)*132 + d0) = hv;                 // conflict-free
        *(float4*)(&g_h[obase[j0+jj] + d0]) = hv;               // coalesced per warp
    }
    __syncthreads();

    // Stage 2: q = relu(Wp @ h + bp)
    for (int i = tid; i < Cc*Cc; i += 256) {
        int d = i >> 7, c = i & 127;
        Ws[c*132 + d] = Wp[i];
    }
    if (tid < Cc) bs[tid] = bpv[tid];
    __syncthreads();

    #pragma unroll
    for (int i = 0; i < 4; i++)
        #pragma unroll
        for (int j = 0; j < 4; j++) acc[i][j] = 0.f;

    #pragma unroll 4
    for (int k = 0; k < Cc; k++) {
        float4 wv = *(const float4*)(Ws + k*132 + d0);
        float h0 = Hs[(j0+0)*132 + k];   // broadcast within warp
        float h1 = Hs[(j0+1)*132 + k];
        float h2 = Hs[(j0+2)*132 + k];
        float h3 = Hs[(j0+3)*132 + k];
        acc[0][0] += wv.x * h0; acc[0][1] += wv.x * h1;
        acc[0][2] += wv.x * h2; acc[0][3] += wv.x * h3;
        acc[1][0] += wv.y * h0; acc[1][1] += wv.y * h1;
        acc[1][2] += wv.y * h2; acc[1][3] += wv.y * h3;
        acc[2][0] += wv.z * h0; acc[2][1] += wv.z * h1;
        acc[2][2] += wv.z * h2; acc[2][3] += wv.z * h3;
        acc[3][0] += wv.w * h0; acc[3][1] += wv.w * h1;
        acc[3][2] += wv.w * h2; acc[3][3] += wv.w * h3;
    }

    bias0 = bs[d0+0]; bias1 = bs[d0+1]; bias2 = bs[d0+2]; bias3 = bs[d0+3];
    #pragma unroll
    for (int jj = 0; jj < 4; jj++) {
        float4 qv;
        qv.x = fmaxf(acc[0][jj] + bias0, 0.f);
        qv.y = fmaxf(acc[1][jj] + bias1, 0.f);
        qv.z = fmaxf(acc[2][jj] + bias2, 0.f);
        qv.w = fmaxf(acc[3][jj] + bias3, 0.f);
        *(float4*)(&g_q[obase[j0+jj] + d0]) = qv;
    }
}

// ---------------------------------------------------------------------------
// Kernel 2: per 32-column tile, build cat = [h ; max_k q[:, idx[n,k]]] in smem,
//           then out = relu(W2 @ cat + b2). Thread tile: 32 rows x 1 col
//           (lane = column) so output stores are coalesced along n.
// ---------------------------------------------------------------------------
__global__ __launch_bounds__(256, 2)
void k2(const int* __restrict__ eidx, const float* __restrict__ W2,
        const float* __restrict__ b2v, float* __restrict__ out)
{
    extern __shared__ float smem[];
    float* Cs  = smem;                 // [256][33] cat tile (pad 33)
    float* W2s = Cs + 256*33;          // [64][260] transposed W2 K-slice
    float* bs  = W2s + 64*260;         // [256]
    int* idxs  = (int*)(bs + 256);     // [32][16] neighbor indices
    int* qb    = idxs + TN*Kk;         // [32] gather base b*N*C
    int* ob    = qb + 32;              // [32] output base b*N*CO + n

    const int tid  = threadIdx.x;
    const int col0 = blockIdx.x * TN;

    if (tid < TN) {
        int col = col0 + tid;
        int b = col / Nn;
        int n = col - b * Nn;
        qb[tid] = b * (Nn * Cc);
        ob[tid] = b * (Nn * CO) + n;
    }
    bs[tid & 255] = b2v[tid & 255];
    for (int i = tid; i < TN*Kk; i += 256)
        idxs[i] = eidx[col0*Kk + i];     // edge_index[0][b][n][k] = eidx[col*16+k]
    __syncthreads();

    // Top half of cat: h columns
    for (int i = tid; i < Cc*TN; i += 256) {
        int c = i & 127, j = i >> 7;
        Cs[c*33 + j] = g_h[(col0 + j)*Cc + c];
    }
    // Bottom half: gather-max over 16 neighbors (512B-contiguous column reads)
    for (int i = tid; i < Cc*TN; i += 256) {
        int c = i & 127, j = i >> 7;
        const int* ip = idxs + j*Kk;
        int base = qb[j] + c;
        float m = -3.402823466e38f;
        #pragma unroll
        for (int k = 0; k < Kk; k++)
            m = fmaxf(m, g_q[base + ip[k]*Cc]);
        Cs[(Cc + c)*33 + j] = m;
    }
    __syncthreads();

    const int lane = tid & 31;          // column within tile
    const int d0   = (tid >> 5) * 32;   // 32 output rows per warp

    float acc[32];
    #pragma unroll
    for (int i = 0; i < 32; i++) acc[i] = 0.f;

    for (int s = 0; s < 4; s++) {
        // Stage W2 slice transposed: W2s[kk][d], k = s*64 + kk
        for (int i = tid; i < 64*CO; i += 256) {
            int d = i >> 6, kk = i & 63;
            W2s[kk*260 + d] = W2[d*(2*Cc) + s*64 + kk];
        }
        __syncthreads();
        #pragma unroll 4
        for (int kk = 0; kk < 64; kk++) {
            float cv = Cs[(s*64 + kk)*33 + lane];   // conflict-free, per-lane
            #pragma unroll
            for (int i = 0; i < 8; i++) {
                float4 wv = *(const float4*)(W2s + kk*260 + d0 + i*4); // broadcast
                acc[i*4+0] += wv.x * cv;
                acc[i*4+1] += wv.y * cv;
                acc[i*4+2] += wv.z * cv;
                acc[i*4+3] += wv.w * cv;
            }
        }
        __syncthreads();
    }

    const int base = ob[lane];
    #pragma unroll
    for (int i = 0; i < 32; i++) {
        float v = fmaxf(acc[i] + bs[d0 + i], 0.f);
        out[base + (d0 + i)*Nn] = v;    // coalesced: warp spans 32 consecutive n
    }
}

extern "C" void kernel_launch(void* const* d_in, const int* in_sizes, int n_in,
                              void* d_out, int out_size)
{
    const float* x  = (const float*)d_in[0];
    const int*   ei = (const int*)  d_in[1];
    const float* W1 = (const float*)d_in[2];
    const float* b1 = (const float*)d_in[3];
    const float* Wp = (const float*)d_in[4];
    const float* bp = (const float*)d_in[5];
    const float* W2 = (const float*)d_in[6];
    const float* b2 = (const float*)d_in[7];
    float* out = (float*)d_out;

    const int s1 = (128*132 + 128*32 + 32*132 + 128) * 4 + 64 * 4;
    const int s2 = (256*33 + 64*260 + 256) * 4 + (TN*Kk + 64) * 4;

    cudaFuncSetAttribute(k1, cudaFuncAttributeMaxDynamicSharedMemorySize, s1);
    cudaFuncSetAttribute(k2, cudaFuncAttributeMaxDynamicSharedMemorySize, s2);

    k1<<<NT/TN, 256, s1>>>(x, W1, b1, Wp, bp);
    k2<<<NT/TN, 256, s2>>>(ei, W2, b2, out);
}

// round 2
// speedup vs baseline: 1.0010x; 1.0010x over previous
#include <cuda_runtime.h>

#define Bc 8
#define Cc 128
#define Nn 10000
#define Kk 16
#define CO 256
#define NT (Bc*Nn)   // 80000 total columns
#define TN 32        // columns per block

// Scratch: node-major (B,N,C) layouts so neighbor gathers are contiguous 512B columns.
__device__ float g_h[NT*Cc];
__device__ float g_q[NT*Cc];

// ---------------------------------------------------------------------------
// Kernel 1: per 32-column tile, compute h = relu(W1 @ x + b1) and
//           q = relu(Wp @ h + bp). Both stored node-major: buf[(b*N+n)*C + d].
// Block: 256 threads, thread tile 4 rows x 4 cols.
// ---------------------------------------------------------------------------
__global__ __launch_bounds__(256, 2)
void k1(const float* __restrict__ x, const float* __restrict__ W1,
        const float* __restrict__ b1v, const float* __restrict__ Wp,
        const float* __restrict__ bpv)
{
    extern __shared__ float smem[];
    float* Ws = smem;                  // [128][132] transposed weights (pad 132)
    float* Xs = Ws + 128*132;          // [128][32]  K-major input tile
    float* Hs = Xs + 128*32;           // [32][132]  h tile, column-major per node
    float* bs = Hs + 32*132;           // [128] bias
    int* xbase = (int*)(bs + 128);     // [32] per-column x base
    int* obase = xbase + 32;           // [32] per-column output base (col*128)

    const int tid  = threadIdx.x;
    const int col0 = blockIdx.x * TN;

    if (tid < TN) {
        int col = col0 + tid;
        int b = col / Nn;
        int n = col - b * Nn;
        xbase[tid] = b * (Cc * Nn) + n;   // x[b][c][n] = x[xbase + c*Nn]
        obase[tid] = col * Cc;
    }
    // W1 transposed into Ws[c][d]
    for (int i = tid; i < Cc*Cc; i += 256) {
        int d = i >> 7, c = i & 127;
        Ws[c*132 + d] = W1[i];
    }
    if (tid < Cc) bs[tid] = b1v[tid];
    __syncthreads();

    // X tile: Xs[c][j]
    for (int i = tid; i < Cc*TN; i += 256) {
        int c = i >> 5, j = i & 31;
        Xs[c*32 + j] = x[xbase[j] + c * Nn];
    }
    __syncthreads();

    const int d0 = (tid & 31) * 4;   // row group (output channel)
    const int j0 = (tid >> 5) * 4;   // column group

    float acc[4][4];
    #pragma unroll
    for (int i = 0; i < 4; i++)
        #pragma unroll
        for (int j = 0; j < 4; j++) acc[i][j] = 0.f;

    #pragma unroll 4
    for (int k = 0; k < Cc; k++) {
        float4 wv = *(const float4*)(Ws + k*132 + d0);
        float4 xv = *(const float4*)(Xs + k*32  + j0);
        acc[0][0] += wv.x * xv.x; acc[0][1] += wv.x * xv.y;
        acc[0][2] += wv.x * xv.z; acc[0][3] += wv.x * xv.w;
        acc[1][0] += wv.y * xv.x; acc[1][1] += wv.y * xv.y;
        acc[1][2] += wv.y * xv.z; acc[1][3] += wv.y * xv.w;
        acc[2][0] += wv.z * xv.x; acc[2][1] += wv.z * xv.y;
        acc[2][2] += wv.z * xv.z; acc[2][3] += wv.z * xv.w;
        acc[3][0] += wv.w * xv.x; acc[3][1] += wv.w * xv.y;
        acc[3][2] += wv.w * xv.z; acc[3][3] += wv.w * xv.w;
    }

    float bias0 = bs[d0+0], bias1 = bs[d0+1], bias2 = bs[d0+2], bias3 = bs[d0+3];
    #pragma unroll
    for (int jj = 0; jj < 4; jj++) {
        float4 hv;
        hv.x = fmaxf(acc[0][jj] + bias0, 0.f);
        hv.y = fmaxf(acc[1][jj] + bias1, 0.f);
        hv.z = fmaxf(acc[2][jj] + bias2, 0.f);
        hv.w = fmaxf(acc[3][jj] + bias3, 0.f);
        *(float4*)(Hs + (j0+jj)*132 + d0) = hv;                 // conflict-free
        *(float4*)(&g_h[obase[j0+jj] + d0]) = hv;               // coalesced per warp
    }
    __syncthreads();

    // Stage 2: q = relu(Wp @ h + bp)
    for (int i = tid; i < Cc*Cc; i += 256) {
        int d = i >> 7, c = i & 127;
        Ws[c*132 + d] = Wp[i];
    }
    if (tid < Cc) bs[tid] = bpv[tid];
    __syncthreads();

    #pragma unroll
    for (int i = 0; i < 4; i++)
        #pragma unroll
        for (int j = 0; j < 4; j++) acc[i][j] = 0.f;

    #pragma unroll 4
    for (int k = 0; k < Cc; k++) {
        float4 wv = *(const float4*)(Ws + k*132 + d0);
        float h0 = Hs[(j0+0)*132 + k];   // broadcast within warp
        float h1 = Hs[(j0+1)*132 + k];
        float h2 = Hs[(j0+2)*132 + k];
        float h3 = Hs[(j0+3)*132 + k];
        acc[0][0] += wv.x * h0; acc[0][1] += wv.x * h1;
        acc[0][2] += wv.x * h2; acc[0][3] += wv.x * h3;
        acc[1][0] += wv.y * h0; acc[1][1] += wv.y * h1;
        acc[1][2] += wv.y * h2; acc[1][3] += wv.y * h3;
        acc[2][0] += wv.z * h0; acc[2][1] += wv.z * h1;
        acc[2][2] += wv.z * h2; acc[2][3] += wv.z * h3;
        acc[3][0] += wv.w * h0; acc[3][1] += wv.w * h1;
        acc[3][2] += wv.w * h2; acc[3][3] += wv.w * h3;
    }

    bias0 = bs[d0+0]; bias1 = bs[d0+1]; bias2 = bs[d0+2]; bias3 = bs[d0+3];
    #pragma unroll
    for (int jj = 0; jj < 4; jj++) {
        float4 qv;
        qv.x = fmaxf(acc[0][jj] + bias0, 0.f);
        qv.y = fmaxf(acc[1][jj] + bias1, 0.f);
        qv.z = fmaxf(acc[2][jj] + bias2, 0.f);
        qv.w = fmaxf(acc[3][jj] + bias3, 0.f);
        *(float4*)(&g_q[obase[j0+jj] + d0]) = qv;
    }
}

// ---------------------------------------------------------------------------
// Kernel 2: per 32-column tile, build cat = [h ; max_k q[:, idx[n,k]]] in smem,
//           then out = relu(W2 @ cat + b2). Thread tile: 32 rows x 1 col
//           (lane = column) so output stores are coalesced along n.
// ---------------------------------------------------------------------------
__global__ __launch_bounds__(256, 2)
void k2(const int* __restrict__ eidx, const float* __restrict__ W2,
        const float* __restrict__ b2v, float* __restrict__ out)
{
    extern __shared__ float smem[];
    float* Cs  = smem;                 // [256][33] cat tile (pad 33)
    float* W2s = Cs + 256*33;          // [64][260] transposed W2 K-slice
    float* bs  = W2s + 64*260;         // [256]
    int* idxs  = (int*)(bs + 256);     // [32][16] neighbor indices
    int* qb    = idxs + TN*Kk;         // [32] gather base b*N*C
    int* ob    = qb + 32;              // [32] output base b*N*CO + n

    const int tid  = threadIdx.x;
    const int col0 = blockIdx.x * TN;

    if (tid < TN) {
        int col = col0 + tid;
        int b = col / Nn;
        int n = col - b * Nn;
        qb[tid] = b * (Nn * Cc);
        ob[tid] = b * (Nn * CO) + n;
    }
    bs[tid & 255] = b2v[tid & 255];
    for (int i = tid; i < TN*Kk; i += 256)
        idxs[i] = eidx[col0*Kk + i];     // edge_index[0][b][n][k] = eidx[col*16+k]
    __syncthreads();

    // Top half of cat: h columns
    for (int i = tid; i < Cc*TN; i += 256) {
        int c = i & 127, j = i >> 7;
        Cs[c*33 + j] = g_h[(col0 + j)*Cc + c];
    }
    // Bottom half: gather-max over 16 neighbors (512B-contiguous column reads)
    for (int i = tid; i < Cc*TN; i += 256) {
        int c = i & 127, j = i >> 7;
        const int* ip = idxs + j*Kk;
        int base = qb[j] + c;
        float m = -3.402823466e38f;
        #pragma unroll
        for (int k = 0; k < Kk; k++)
            m = fmaxf(m, g_q[base + ip[k]*Cc]);
        Cs[(Cc + c)*33 + j] = m;
    }
    __syncthreads();

    const int lane = tid & 31;          // column within tile
    const int d0   = (tid >> 5) * 32;   // 32 output rows per warp

    float acc[32];
    #pragma unroll
    for (int i = 0; i < 32; i++) acc[i] = 0.f;

    for (int s = 0; s < 4; s++) {
        // Stage W2 slice transposed: W2s[kk][d], k = s*64 + kk
        for (int i = tid; i < 64*CO; i += 256) {
            int d = i >> 6, kk = i & 63;
            W2s[kk*260 + d] = W2[d*(2*Cc) + s*64 + kk];
        }
        __syncthreads();
        #pragma unroll 4
        for (int kk = 0; kk < 64; kk++) {
            float cv = Cs[(s*64 + kk)*33 + lane];   // conflict-free, per-lane
            #pragma unroll
            for (int i = 0; i < 8; i++) {
                float4 wv = *(const float4*)(W2s + kk*260 + d0 + i*4); // broadcast
                acc[i*4+0] += wv.x * cv;
                acc[i*4+1] += wv.y * cv;
                acc[i*4+2] += wv.z * cv;
                acc[i*4+3] += wv.w * cv;
            }
        }
        __syncthreads();
    }

    const int base = ob[lane];
    #pragma unroll
    for (int i = 0; i < 32; i++) {
        float v = fmaxf(acc[i] + bs[d0 + i], 0.f);
        out[base + (d0 + i)*Nn] = v;    // coalesced: warp spans 32 consecutive n
    }
}

extern "C" void kernel_launch(void* const* d_in, const int* in_sizes, int n_in,
                              void* d_out, int out_size)
{
    const float* x  = (const float*)d_in[0];
    const int*   ei = (const int*)  d_in[1];
    const float* W1 = (const float*)d_in[2];
    const float* b1 = (const float*)d_in[3];
    const float* Wp = (const float*)d_in[4];
    const float* bp = (const float*)d_in[5];
    const float* W2 = (const float*)d_in[6];
    const float* b2 = (const float*)d_in[7];
    float* out = (float*)d_out;

    const int s1 = (128*132 + 128*32 + 32*132 + 128) * 4 + 64 * 4;
    const int s2 = (256*33 + 64*260 + 256) * 4 + (TN*Kk + 64) * 4;

    cudaFuncSetAttribute(k1, cudaFuncAttributeMaxDynamicSharedMemorySize, s1);
    cudaFuncSetAttribute(k2, cudaFuncAttributeMaxDynamicSharedMemorySize, s2);

    k1<<<NT/TN, 256, s1>>>(x, W1, b1, Wp, bp);
    k2<<<NT/TN, 256, s2>>>(ei, W2, b2, out);
}

// round 5
// speedup vs baseline: 2.2735x; 2.2713x over previous
#include <cuda_runtime.h>
#include <cuda_bf16.h>
#include <cstdint>

#define Bb 8
#define Cc 128
#define Nn 10000
#define Kk 16
#define CO 256
#define NT (Bb*Nn)
#define S1 136              // padded smem stride (elements) -> 272B, conflict-free frags

// ---------------------------------------------------------------------------
// Device scratch
// ---------------------------------------------------------------------------
// Weight images (bf16 hi/lo, plain row-major):
// [W1hi 16384][W1lo 16384][Wphi 16384][Wplo 16384][W2hi 65536][W2lo 65536]
__device__ __align__(16) __nv_bfloat16 g_wimg[4*16384 + 2*65536];
__device__ __align__(16) __nv_bfloat16 g_cat_hi[(size_t)NT*256];
__device__ __align__(16) __nv_bfloat16 g_cat_lo[(size_t)NT*256];
__device__ __align__(16) float g_q[(size_t)NT*128];

__device__ __forceinline__ void split_bf16(float v, __nv_bfloat16& h, __nv_bfloat16& l) {
    h = __float2bfloat16(v);
    l = __float2bfloat16(v - __bfloat162float(h));
}

// D(16x8,f32) += A(16x16,bf16 row) * B(16x8,bf16 col)
__device__ __forceinline__ void mma_bf16(float* d, const uint32_t* a, const uint32_t* b) {
    asm("mma.sync.aligned.m16n8k16.row.col.f32.bf16.bf16.f32 "
        "{%0,%1,%2,%3}, {%4,%5,%6,%7}, {%8,%9}, {%0,%1,%2,%3};"
        : "+f"(d[0]), "+f"(d[1]), "+f"(d[2]), "+f"(d[3])
        : "r"(a[0]), "r"(a[1]), "r"(a[2]), "r"(a[3]), "r"(b[0]), "r"(b[1]));
}

// Warp GEMM, tile 32(M) x 64(N), K=128, 3-term hi/lo split.
// A[m][k] row-major stride S1, B[n][k] "col-major" (k contiguous) stride S1.
__device__ __forceinline__ void gemm_2x8(float acc[2][8][4],
        const __nv_bfloat16* WH, const __nv_bfloat16* WL,
        const __nv_bfloat16* BH, const __nv_bfloat16* BL,
        int m0, int n0, int r, int c)
{
    #pragma unroll
    for (int t = 0; t < 3; t++) {
        const __nv_bfloat16* Ap = (t == 2) ? WL : WH;
        const __nv_bfloat16* Bp = (t == 1) ? BL : BH;
        #pragma unroll
        for (int kk = 0; kk < 8; kk++) {
            const int k0 = kk * 16;
            uint32_t a[2][4];
            #pragma unroll
            for (int mi = 0; mi < 2; mi++) {
                const __nv_bfloat16* p = Ap + (m0 + mi*16 + r)*S1 + k0 + c;
                a[mi][0] = *(const uint32_t*)p;
                a[mi][1] = *(const uint32_t*)(p + 8*S1);
                a[mi][2] = *(const uint32_t*)(p + 8);
                a[mi][3] = *(const uint32_t*)(p + 8*S1 + 8);
            }
            #pragma unroll
            for (int ni = 0; ni < 8; ni++) {
                const __nv_bfloat16* p = Bp + (n0 + ni*8 + r)*S1 + k0 + c;
                uint32_t b[2];
                b[0] = *(const uint32_t*)p;
                b[1] = *(const uint32_t*)(p + 8);
                mma_bf16(acc[0][ni], a[0], b);
                mma_bf16(acc[1][ni], a[1], b);
            }
        }
    }
}

// Warp GEMM, tile 64(M) x 64(N), K=128 slice, 3-term split, accumulate.
__device__ __forceinline__ void gemm_4x8(float acc[4][8][4],
        const __nv_bfloat16* WH, const __nv_bfloat16* WL,
        const __nv_bfloat16* BH, const __nv_bfloat16* BL,
        int m0, int n0, int r, int c)
{
    #pragma unroll
    for (int t = 0; t < 3; t++) {
        const __nv_bfloat16* Ap = (t == 2) ? WL : WH;
        const __nv_bfloat16* Bp = (t == 1) ? BL : BH;
        #pragma unroll
        for (int kk = 0; kk < 8; kk++) {
            const int k0 = kk * 16;
            uint32_t a[4][4];
            #pragma unroll
            for (int mi = 0; mi < 4; mi++) {
                const __nv_bfloat16* p = Ap + (m0 + mi*16 + r)*S1 + k0 + c;
                a[mi][0] = *(const uint32_t*)p;
                a[mi][1] = *(const uint32_t*)(p + 8*S1);
                a[mi][2] = *(const uint32_t*)(p + 8);
                a[mi][3] = *(const uint32_t*)(p + 8*S1 + 8);
            }
            #pragma unroll
            for (int ni = 0; ni < 8; ni++) {
                const __nv_bfloat16* p = Bp + (n0 + ni*8 + r)*S1 + k0 + c;
                uint32_t b[2];
                b[0] = *(const uint32_t*)p;
                b[1] = *(const uint32_t*)(p + 8);
                #pragma unroll
                for (int mi = 0; mi < 4; mi++)
                    mma_bf16(acc[mi][ni], a[mi], b);
            }
        }
    }
}

// ---------------------------------------------------------------------------
// kw: one-time split of weights into bf16 hi/lo global images
// ---------------------------------------------------------------------------
__global__ void kw(const float* __restrict__ W1, const float* __restrict__ Wp,
                   const float* __restrict__ W2) {
    int t = blockIdx.x * 256 + threadIdx.x;     // 98304
    __nv_bfloat16 h, l;
    if (t < 16384) {
        split_bf16(W1[t], h, l);
        g_wimg[t] = h; g_wimg[16384 + t] = l;
    } else if (t < 32768) {
        int e = t - 16384;
        split_bf16(Wp[e], h, l);
        g_wimg[32768 + e] = h; g_wimg[49152 + e] = l;
    } else {
        int e = t - 32768;
        split_bf16(W2[e], h, l);
        g_wimg[65536 + e] = h; g_wimg[131072 + e] = l;
    }
}

// ---------------------------------------------------------------------------
// k1: per 128-node tile: h = relu(W1@x+b1); q = relu(Wp@h+bp)
//     h -> g_cat channels 0-127 (bf16 hi/lo), q -> g_q (fp32)
// smem: [xb 512][WA hi/lo 69632][BB hi/lo 69632] = 139776
// ---------------------------------------------------------------------------
__global__ __launch_bounds__(256, 1)
void k1(const float* __restrict__ x, const float* __restrict__ b1v,
        const float* __restrict__ bpv)
{
    extern __shared__ unsigned char sm[];
    int* xb = (int*)sm;
    __nv_bfloat16* WH = (__nv_bfloat16*)(sm + 512);
    __nv_bfloat16* WL = WH + 128*S1;
    __nv_bfloat16* BH = (__nv_bfloat16*)(sm + 512 + 69632);
    __nv_bfloat16* BL = BH + 128*S1;
    float* Q = (float*)BH;                 // overlay after GEMM2 (stride 132)

    const int tid = threadIdx.x, lane = tid & 31, wid = tid >> 5;
    const int r = lane >> 2, c = (lane & 3) * 2;
    const int wm = wid >> 1, wn = wid & 1;
    const int m0 = wm * 32, n0 = wn * 64;
    const int col0 = blockIdx.x * 128;

    if (tid < 128) {
        int col = col0 + tid, b = col / Nn;
        xb[tid] = b * (Cc * Nn) + (col - b * Nn);
    }
    {   // W1 hi/lo -> smem (u32, conflict-free)
        const uint32_t* sH = (const uint32_t*)g_wimg;          // W1hi
        const uint32_t* sL = sH + 8192;                         // W1lo
        uint32_t* dH = (uint32_t*)WH;
        uint32_t* dL = (uint32_t*)WL;
        #pragma unroll 4
        for (int i = tid; i < 8192; i += 256) {
            int m = i >> 6, w = i & 63;
            dH[m*68 + w] = sH[i];
            dL[m*68 + w] = sL[i];
        }
    }
    __syncthreads();

    // x tile -> B planes (node-major, split)
    for (int i = tid; i < 16384; i += 256) {
        int j = i & 127, ch = i >> 7;
        float v = x[xb[j] + ch * Nn];
        __nv_bfloat16 h, l; split_bf16(v, h, l);
        BH[j*S1 + ch] = h;
        BL[j*S1 + ch] = l;
    }
    __syncthreads();

    float acc[2][8][4];
    #pragma unroll
    for (int i = 0; i < 2; i++)
        #pragma unroll
        for (int j = 0; j < 8; j++)
            #pragma unroll
            for (int v = 0; v < 4; v++) acc[i][j][v] = 0.f;

    gemm_2x8(acc, WH, WL, BH, BL, m0, n0, r, c);
    __syncthreads();

    // Epilogue 1: h -> B planes (overwrite x) ; also copy Wp into WA
    #pragma unroll
    for (int mi = 0; mi < 2; mi++) {
        int mr = m0 + mi*16 + r;
        float bias_a = b1v[mr], bias_b = b1v[mr + 8];
        #pragma unroll
        for (int ni = 0; ni < 8; ni++) {
            int nc = n0 + ni*8 + c;
            __nv_bfloat16 h, l;
            float v;
            v = fmaxf(acc[mi][ni][0] + bias_a, 0.f); split_bf16(v, h, l);
            BH[nc*S1 + mr] = h;       BL[nc*S1 + mr] = l;
            v = fmaxf(acc[mi][ni][1] + bias_a, 0.f); split_bf16(v, h, l);
            BH[(nc+1)*S1 + mr] = h;   BL[(nc+1)*S1 + mr] = l;
            v = fmaxf(acc[mi][ni][2] + bias_b, 0.f); split_bf16(v, h, l);
            BH[nc*S1 + mr+8] = h;     BL[nc*S1 + mr+8] = l;
            v = fmaxf(acc[mi][ni][3] + bias_b, 0.f); split_bf16(v, h, l);
            BH[(nc+1)*S1 + mr+8] = h; BL[(nc+1)*S1 + mr+8] = l;
        }
    }
    {   // Wp hi/lo -> WA
        const uint32_t* sH = (const uint32_t*)(g_wimg + 32768);
        const uint32_t* sL = (const uint32_t*)(g_wimg + 49152);
        uint32_t* dH = (uint32_t*)WH;
        uint32_t* dL = (uint32_t*)WL;
        #pragma unroll 4
        for (int i = tid; i < 8192; i += 256) {
            int m = i >> 6, w = i & 63;
            dH[m*68 + w] = sH[i];
            dL[m*68 + w] = sL[i];
        }
    }
    __syncthreads();

    // Copy h rows to g_cat (coalesced uint4) while GEMM2 runs on same data
    for (int i = tid; i < 2048; i += 256) {
        int j = i >> 4, v = i & 15;
        ((uint4*)(g_cat_hi + (size_t)(col0 + j) * 256))[v] = ((const uint4*)(BH + j*S1))[v];
        ((uint4*)(g_cat_lo + (size_t)(col0 + j) * 256))[v] = ((const uint4*)(BL + j*S1))[v];
    }

    #pragma unroll
    for (int i = 0; i < 2; i++)
        #pragma unroll
        for (int j = 0; j < 8; j++)
            #pragma unroll
            for (int v = 0; v < 4; v++) acc[i][j][v] = 0.f;

    gemm_2x8(acc, WH, WL, BH, BL, m0, n0, r, c);
    __syncthreads();      // all reads of BB done before Q overlays it

    // Epilogue 2: q -> Q staging (fp32, stride 132)
    #pragma unroll
    for (int mi = 0; mi < 2; mi++) {
        int mr = m0 + mi*16 + r;
        float bias_a = bpv[mr], bias_b = bpv[mr + 8];
        #pragma unroll
        for (int ni = 0; ni < 8; ni++) {
            int nc = n0 + ni*8 + c;
            Q[nc*132 + mr]       = fmaxf(acc[mi][ni][0] + bias_a, 0.f);
            Q[(nc+1)*132 + mr]   = fmaxf(acc[mi][ni][1] + bias_a, 0.f);
            Q[nc*132 + mr+8]     = fmaxf(acc[mi][ni][2] + bias_b, 0.f);
            Q[(nc+1)*132 + mr+8] = fmaxf(acc[mi][ni][3] + bias_b, 0.f);
        }
    }
    __syncthreads();

    // Coalesced q -> global (float4)
    for (int i = tid; i < 4096; i += 256) {
        int j = i >> 5, v = i & 31;
        ((float4*)(g_q + (size_t)(col0 + j) * 128))[v] = ((const float4*)(Q + j*132))[v];
    }
}

// ---------------------------------------------------------------------------
// kg: warp-per-node gather-max over 16 neighbors -> g_cat channels 128-255
// ---------------------------------------------------------------------------
__global__ __launch_bounds__(256, 4)
void kg(const int* __restrict__ eidx) {
    const int wid = threadIdx.x >> 5, lane = threadIdx.x & 31;
    const int col = blockIdx.x * 8 + wid;
    const int b = col / Nn;
    int id = 0;
    if (lane < Kk) id = eidx[col * Kk + lane];
    const float* qb = g_q + (size_t)b * Nn * 128;
    float4 m = make_float4(0.f, 0.f, 0.f, 0.f);   // relu output >= 0
    #pragma unroll
    for (int k = 0; k < Kk; k++) {
        int nb = __shfl_sync(0xffffffffu, id, k);
        float4 v = *((const float4*)(qb + (size_t)nb * 128) + lane);
        m.x = fmaxf(m.x, v.x); m.y = fmaxf(m.y, v.y);
        m.z = fmaxf(m.z, v.z); m.w = fmaxf(m.w, v.w);
    }
    __nv_bfloat16 h0,l0,h1,l1,h2,l2,h3,l3;
    split_bf16(m.x, h0, l0); split_bf16(m.y, h1, l1);
    split_bf16(m.z, h2, l2); split_bf16(m.w, h3, l3);
    size_t base = (size_t)col * 256 + 128 + lane * 4;
    *(__nv_bfloat162*)(g_cat_hi + base)     = __nv_bfloat162{h0, h1};
    *(__nv_bfloat162*)(g_cat_hi + base + 2) = __nv_bfloat162{h2, h3};
    *(__nv_bfloat162*)(g_cat_lo + base)     = __nv_bfloat162{l0, l1};
    *(__nv_bfloat162*)(g_cat_lo + base + 2) = __nv_bfloat162{l2, l3};
}

// ---------------------------------------------------------------------------
// k2: out = relu(W2 @ cat + b2). M=256, N=128/block, K=256 in two smem phases.
// smem: [A hi/lo 139264][B hi/lo 69632] = 208896
// ---------------------------------------------------------------------------
__global__ __launch_bounds__(256, 1)
void k2(const float* __restrict__ b2v, float* __restrict__ out)
{
    extern __shared__ unsigned char sm[];
    __nv_bfloat16* WH = (__nv_bfloat16*)sm;          // 256 x S1
    __nv_bfloat16* WL = WH + 256*S1;
    __nv_bfloat16* BH = (__nv_bfloat16*)(sm + 139264);
    __nv_bfloat16* BL = BH + 128*S1;

    const int tid = threadIdx.x, lane = tid & 31, wid = tid >> 5;
    const int r = lane >> 2, c = (lane & 3) * 2;
    const int wm = wid >> 1, wn = wid & 1;
    const int m0 = wm * 64, n0 = wn * 64;
    const int col0 = blockIdx.x * 128;

    float acc[4][8][4];
    #pragma unroll
    for (int i = 0; i < 4; i++)
        #pragma unroll
        for (int j = 0; j < 8; j++)
            #pragma unroll
            for (int v = 0; v < 4; v++) acc[i][j][v] = 0.f;

    for (int kh = 0; kh < 2; kh++) {
        {   // A: W2 K-half slice hi/lo (u32, conflict-free smem writes)
            const uint32_t* sH = (const uint32_t*)(g_wimg + 65536);
            const uint32_t* sL = (const uint32_t*)(g_wimg + 131072);
            uint32_t* dH = (uint32_t*)WH;
            uint32_t* dL = (uint32_t*)WL;
            #pragma unroll 4
            for (int i = tid; i < 16384; i += 256) {
                int m = i >> 6, w = i & 63;
                dH[m*68 + w] = sH[m*128 + kh*64 + w];
                dL[m*68 + w] = sL[m*128 + kh*64 + w];
            }
        }
        // B: cat K-half slice (uint4 rows)
        for (int i = tid; i < 2048; i += 256) {
            int j = i >> 4, v = i & 15;
            ((uint4*)(BH + j*S1))[v] =
                ((const uint4*)(g_cat_hi + (size_t)(col0 + j) * 256 + kh*128))[v];
            ((uint4*)(BL + j*S1))[v] =
                ((const uint4*)(g_cat_lo + (size_t)(col0 + j) * 256 + kh*128))[v];
        }
        __syncthreads();

        gemm_4x8(acc, WH, WL, BH, BL, m0, n0, r, c);
        __syncthreads();
    }

    // Epilogue: bias + relu + direct store, out[b][d][node]
    #pragma unroll
    for (int mi = 0; mi < 4; mi++) {
        int mr = m0 + mi*16 + r;
        float bias_a = b2v[mr], bias_b = b2v[mr + 8];
        #pragma unroll
        for (int ni = 0; ni < 8; ni++) {
            int nc = n0 + ni*8 + c;
            int colA = col0 + nc, colB = colA + 1;
            int ba = colA / Nn, bb = colB / Nn;
            size_t obA = (size_t)ba * CO * Nn + (colA - ba * Nn);
            size_t obB = (size_t)bb * CO * Nn + (colB - bb * Nn);
            out[obA + (size_t)mr * Nn]     = fmaxf(acc[mi][ni][0] + bias_a, 0.f);
            out[obB + (size_t)mr * Nn]     = fmaxf(acc[mi][ni][1] + bias_a, 0.f);
            out[obA + (size_t)(mr+8) * Nn] = fmaxf(acc[mi][ni][2] + bias_b, 0.f);
            out[obB + (size_t)(mr+8) * Nn] = fmaxf(acc[mi][ni][3] + bias_b, 0.f);
        }
    }
}

// ---------------------------------------------------------------------------
extern "C" void kernel_launch(void* const* d_in, const int* in_sizes, int n_in,
                              void* d_out, int out_size)
{
    const float* x  = (const float*)d_in[0];
    const int*   ei = (const int*)  d_in[1];
    const float* W1 = (const float*)d_in[2];
    const float* b1 = (const float*)d_in[3];
    const float* Wp = (const float*)d_in[4];
    const float* bp = (const float*)d_in[5];
    const float* W2 = (const float*)d_in[6];
    const float* b2 = (const float*)d_in[7];
    float* out = (float*)d_out;

    const int s1 = 139776;
    const int s2 = 208896;
    cudaFuncSetAttribute(k1, cudaFuncAttributeMaxDynamicSharedMemorySize, s1);
    cudaFuncSetAttribute(k2, cudaFuncAttributeMaxDynamicSharedMemorySize, s2);

    kw<<<384, 256>>>(W1, Wp, W2);
    k1<<<NT / 128, 256, s1>>>(x, b1, bp);
    kg<<<NT / 8, 256>>>(ei);
    k2<<<NT / 128, 256, s2>>>(b2, out);
}

// round 6
// speedup vs baseline: 2.7919x; 1.2280x over previous
#include <cuda_runtime.h>
#include <cuda_bf16.h>
#include <cstdint>

#define Bb 8
#define Cc 128
#define Nn 10000
#define Kk 16
#define CO 256
#define NT (Bb*Nn)
#define S1 136              // padded smem stride (elements) -> 272B, conflict-free frags
#define SK 72               // k2 chunk stride (64 k-elems + 8 pad) -> r*4 bank pattern

// ---------------------------------------------------------------------------
// Device scratch
// ---------------------------------------------------------------------------
// Weight images (bf16 hi/lo, plain row-major):
// [W1hi 16384][W1lo 16384][Wphi 16384][Wplo 16384][W2hi 65536][W2lo 65536]
__device__ __align__(16) __nv_bfloat16 g_wimg[4*16384 + 2*65536];
__device__ __align__(16) __nv_bfloat16 g_cat_hi[(size_t)NT*256];
__device__ __align__(16) __nv_bfloat16 g_cat_lo[(size_t)NT*256];
__device__ __align__(16) float g_q[(size_t)NT*128];

__device__ __forceinline__ void split_bf16(float v, __nv_bfloat16& h, __nv_bfloat16& l) {
    h = __float2bfloat16(v);
    l = __float2bfloat16(v - __bfloat162float(h));
}

// D(16x8,f32) += A(16x16,bf16 row) * B(16x8,bf16 col)
__device__ __forceinline__ void mma_bf16(float* d, const uint32_t* a, const uint32_t* b) {
    asm("mma.sync.aligned.m16n8k16.row.col.f32.bf16.bf16.f32 "
        "{%0,%1,%2,%3}, {%4,%5,%6,%7}, {%8,%9}, {%0,%1,%2,%3};"
        : "+f"(d[0]), "+f"(d[1]), "+f"(d[2]), "+f"(d[3])
        : "r"(a[0]), "r"(a[1]), "r"(a[2]), "r"(a[3]), "r"(b[0]), "r"(b[1]));
}

__device__ __forceinline__ uint32_t s2u(const void* p) {
    uint32_t a;
    asm("{ .reg .u64 t; cvta.to.shared.u64 t, %1; cvt.u32.u64 %0, t; }" : "=r"(a) : "l"(p));
    return a;
}
__device__ __forceinline__ void cp16(uint32_t dst, const void* src) {
    asm volatile("cp.async.cg.shared.global [%0], [%1], 16;" :: "r"(dst), "l"(src));
}
#define CP_COMMIT() asm volatile("cp.async.commit_group;" ::: "memory")
#define CP_WAIT(N)  asm volatile("cp.async.wait_group %0;" :: "n"(N) : "memory")

// Warp GEMM, tile 32(M) x 64(N), K=128, 3-term hi/lo split (k1 path, stride S1).
__device__ __forceinline__ void gemm_2x8(float acc[2][8][4],
        const __nv_bfloat16* WH, const __nv_bfloat16* WL,
        const __nv_bfloat16* BH, const __nv_bfloat16* BL,
        int m0, int n0, int r, int c)
{
    #pragma unroll
    for (int t = 0; t < 3; t++) {
        const __nv_bfloat16* Ap = (t == 2) ? WL : WH;
        const __nv_bfloat16* Bp = (t == 1) ? BL : BH;
        #pragma unroll
        for (int kk = 0; kk < 8; kk++) {
            const int k0 = kk * 16;
            uint32_t a[2][4];
            #pragma unroll
            for (int mi = 0; mi < 2; mi++) {
                const __nv_bfloat16* p = Ap + (m0 + mi*16 + r)*S1 + k0 + c;
                a[mi][0] = *(const uint32_t*)p;
                a[mi][1] = *(const uint32_t*)(p + 8*S1);
                a[mi][2] = *(const uint32_t*)(p + 8);
                a[mi][3] = *(const uint32_t*)(p + 8*S1 + 8);
            }
            #pragma unroll
            for (int ni = 0; ni < 8; ni++) {
                const __nv_bfloat16* p = Bp + (n0 + ni*8 + r)*S1 + k0 + c;
                uint32_t b[2];
                b[0] = *(const uint32_t*)p;
                b[1] = *(const uint32_t*)(p + 8);
                mma_bf16(acc[0][ni], a[0], b);
                mma_bf16(acc[1][ni], a[1], b);
            }
        }
    }
}

// ---------------------------------------------------------------------------
// kw: one-time split of weights into bf16 hi/lo global images
// ---------------------------------------------------------------------------
__global__ void kw(const float* __restrict__ W1, const float* __restrict__ Wp,
                   const float* __restrict__ W2) {
    int t = blockIdx.x * 256 + threadIdx.x;     // 98304
    __nv_bfloat16 h, l;
    if (t < 16384) {
        split_bf16(W1[t], h, l);
        g_wimg[t] = h; g_wimg[16384 + t] = l;
    } else if (t < 32768) {
        int e = t - 16384;
        split_bf16(Wp[e], h, l);
        g_wimg[32768 + e] = h; g_wimg[49152 + e] = l;
    } else {
        int e = t - 32768;
        split_bf16(W2[e], h, l);
        g_wimg[65536 + e] = h; g_wimg[131072 + e] = l;
    }
}

// ---------------------------------------------------------------------------
// k1: per 128-node tile: h = relu(W1@x+b1); q = relu(Wp@h+bp)
//     h -> g_cat channels 0-127 (bf16 hi/lo), q -> g_q (fp32)
// ---------------------------------------------------------------------------
__global__ __launch_bounds__(256, 1)
void k1(const float* __restrict__ x, const float* __restrict__ b1v,
        const float* __restrict__ bpv)
{
    extern __shared__ unsigned char sm[];
    int* xb = (int*)sm;
    __nv_bfloat16* WH = (__nv_bfloat16*)(sm + 512);
    __nv_bfloat16* WL = WH + 128*S1;
    __nv_bfloat16* BH = (__nv_bfloat16*)(sm + 512 + 69632);
    __nv_bfloat16* BL = BH + 128*S1;
    float* Q = (float*)BH;                 // overlay after GEMM2 (stride 132)

    const int tid = threadIdx.x, lane = tid & 31, wid = tid >> 5;
    const int r = lane >> 2, c = (lane & 3) * 2;
    const int wm = wid >> 1, wn = wid & 1;
    const int m0 = wm * 32, n0 = wn * 64;
    const int col0 = blockIdx.x * 128;

    if (tid < 128) {
        int col = col0 + tid, b = col / Nn;
        xb[tid] = b * (Cc * Nn) + (col - b * Nn);
    }
    {   // W1 hi/lo -> smem
        const uint32_t* sH = (const uint32_t*)g_wimg;
        const uint32_t* sL = sH + 8192;
        uint32_t* dH = (uint32_t*)WH;
        uint32_t* dL = (uint32_t*)WL;
        #pragma unroll 4
        for (int i = tid; i < 8192; i += 256) {
            int m = i >> 6, w = i & 63;
            dH[m*68 + w] = sH[i];
            dL[m*68 + w] = sL[i];
        }
    }
    __syncthreads();

    // x tile -> B planes (node-major, split)
    for (int i = tid; i < 16384; i += 256) {
        int j = i & 127, ch = i >> 7;
        float v = x[xb[j] + ch * Nn];
        __nv_bfloat16 h, l; split_bf16(v, h, l);
        BH[j*S1 + ch] = h;
        BL[j*S1 + ch] = l;
    }
    __syncthreads();

    float acc[2][8][4];
    #pragma unroll
    for (int i = 0; i < 2; i++)
        #pragma unroll
        for (int j = 0; j < 8; j++)
            #pragma unroll
            for (int v = 0; v < 4; v++) acc[i][j][v] = 0.f;

    gemm_2x8(acc, WH, WL, BH, BL, m0, n0, r, c);
    __syncthreads();

    // Epilogue 1: h -> B planes ; Wp -> WA
    #pragma unroll
    for (int mi = 0; mi < 2; mi++) {
        int mr = m0 + mi*16 + r;
        float bias_a = b1v[mr], bias_b = b1v[mr + 8];
        #pragma unroll
        for (int ni = 0; ni < 8; ni++) {
            int nc = n0 + ni*8 + c;
            __nv_bfloat16 h, l;
            float v;
            v = fmaxf(acc[mi][ni][0] + bias_a, 0.f); split_bf16(v, h, l);
            BH[nc*S1 + mr] = h;       BL[nc*S1 + mr] = l;
            v = fmaxf(acc[mi][ni][1] + bias_a, 0.f); split_bf16(v, h, l);
            BH[(nc+1)*S1 + mr] = h;   BL[(nc+1)*S1 + mr] = l;
            v = fmaxf(acc[mi][ni][2] + bias_b, 0.f); split_bf16(v, h, l);
            BH[nc*S1 + mr+8] = h;     BL[nc*S1 + mr+8] = l;
            v = fmaxf(acc[mi][ni][3] + bias_b, 0.f); split_bf16(v, h, l);
            BH[(nc+1)*S1 + mr+8] = h; BL[(nc+1)*S1 + mr+8] = l;
        }
    }
    {   // Wp hi/lo -> WA
        const uint32_t* sH = (const uint32_t*)(g_wimg + 32768);
        const uint32_t* sL = (const uint32_t*)(g_wimg + 49152);
        uint32_t* dH = (uint32_t*)WH;
        uint32_t* dL = (uint32_t*)WL;
        #pragma unroll 4
        for (int i = tid; i < 8192; i += 256) {
            int m = i >> 6, w = i & 63;
            dH[m*68 + w] = sH[i];
            dL[m*68 + w] = sL[i];
        }
    }
    __syncthreads();

    // h rows -> g_cat (coalesced uint4)
    for (int i = tid; i < 2048; i += 256) {
        int j = i >> 4, v = i & 15;
        ((uint4*)(g_cat_hi + (size_t)(col0 + j) * 256))[v] = ((const uint4*)(BH + j*S1))[v];
        ((uint4*)(g_cat_lo + (size_t)(col0 + j) * 256))[v] = ((const uint4*)(BL + j*S1))[v];
    }

    #pragma unroll
    for (int i = 0; i < 2; i++)
        #pragma unroll
        for (int j = 0; j < 8; j++)
            #pragma unroll
            for (int v = 0; v < 4; v++) acc[i][j][v] = 0.f;

    gemm_2x8(acc, WH, WL, BH, BL, m0, n0, r, c);
    __syncthreads();

    // Epilogue 2: q -> staging (fp32, stride 132)
    #pragma unroll
    for (int mi = 0; mi < 2; mi++) {
        int mr = m0 + mi*16 + r;
        float bias_a = bpv[mr], bias_b = bpv[mr + 8];
        #pragma unroll
        for (int ni = 0; ni < 8; ni++) {
            int nc = n0 + ni*8 + c;
            Q[nc*132 + mr]       = fmaxf(acc[mi][ni][0] + bias_a, 0.f);
            Q[(nc+1)*132 + mr]   = fmaxf(acc[mi][ni][1] + bias_a, 0.f);
            Q[nc*132 + mr+8]     = fmaxf(acc[mi][ni][2] + bias_b, 0.f);
            Q[(nc+1)*132 + mr+8] = fmaxf(acc[mi][ni][3] + bias_b, 0.f);
        }
    }
    __syncthreads();

    for (int i = tid; i < 4096; i += 256) {
        int j = i >> 5, v = i & 31;
        ((float4*)(g_q + (size_t)(col0 + j) * 128))[v] = ((const float4*)(Q + j*132))[v];
    }
}

// ---------------------------------------------------------------------------
// kg: warp-per-node gather-max over 16 neighbors -> g_cat channels 128-255
// ---------------------------------------------------------------------------
__global__ __launch_bounds__(256, 4)
void kg(const int* __restrict__ eidx) {
    const int wid = threadIdx.x >> 5, lane = threadIdx.x & 31;
    const int col = blockIdx.x * 8 + wid;
    const int b = col / Nn;
    int id = 0;
    if (lane < Kk) id = eidx[col * Kk + lane];
    const float* qb = g_q + (size_t)b * Nn * 128;
    float4 m = make_float4(0.f, 0.f, 0.f, 0.f);   // relu output >= 0
    #pragma unroll
    for (int k = 0; k < Kk; k++) {
        int nb = __shfl_sync(0xffffffffu, id, k);
        float4 v = *((const float4*)(qb + (size_t)nb * 128) + lane);
        m.x = fmaxf(m.x, v.x); m.y = fmaxf(m.y, v.y);
        m.z = fmaxf(m.z, v.z); m.w = fmaxf(m.w, v.w);
    }
    __nv_bfloat16 h0,l0,h1,l1,h2,l2,h3,l3;
    split_bf16(m.x, h0, l0); split_bf16(m.y, h1, l1);
    split_bf16(m.z, h2, l2); split_bf16(m.w, h3, l3);
    size_t base = (size_t)col * 256 + 128 + lane * 4;
    *(__nv_bfloat162*)(g_cat_hi + base)     = __nv_bfloat162{h0, h1};
    *(__nv_bfloat162*)(g_cat_hi + base + 2) = __nv_bfloat162{h2, h3};
    *(__nv_bfloat162*)(g_cat_lo + base)     = __nv_bfloat162{l0, l1};
    *(__nv_bfloat162*)(g_cat_lo + base + 2) = __nv_bfloat162{l2, l3};
}

// ---------------------------------------------------------------------------
// k2: out = relu(W2 @ cat + b2). M=256, N=128/block. K=256 in 4 chunks of 64,
//     double-buffered cp.async. 512 threads, 16 warps, warp tile 32x64.
// smem per stage: AH 36864 | AL 36864 | BH 18432 | BL 18432 = 110592; x2 = 221184
// ---------------------------------------------------------------------------
#define K2_STAGE 110592
#define K2_AH 0
#define K2_AL 36864
#define K2_BH 73728
#define K2_BL 92160

// issue cp.async loads for K-chunk ks into stage buffer
__device__ __forceinline__ void k2_load(unsigned char* sm, uint32_t sbu, int stage,
                                        int ks, int col0, int tid) {
    const uint32_t base = sbu + stage * K2_STAGE;
    // A: W2 slice, 256 rows x 64 bf16, hi+lo
    const __nv_bfloat16* srcH = g_wimg + 65536;
    const __nv_bfloat16* srcL = g_wimg + 131072;
    #pragma unroll
    for (int t = 0; t < 4; t++) {
        int i = tid + t * 512;           // 0..2047
        int m = i >> 3, ch = i & 7;
        int so = m * 256 + ks * 64 + ch * 8;
        uint32_t doff = (uint32_t)(m * SK + ch * 8) * 2;
        cp16(base + K2_AH + doff, srcH + so);
        cp16(base + K2_AL + doff, srcL + so);
    }
    // B: cat slice, 128 nodes x 64 bf16, hi+lo
    #pragma unroll
    for (int t = 0; t < 2; t++) {
        int i = tid + t * 512;           // 0..1023
        int j = i >> 3, ch = i & 7;
        size_t so = (size_t)(col0 + j) * 256 + ks * 64 + ch * 8;
        uint32_t doff = (uint32_t)(j * SK + ch * 8) * 2;
        cp16(base + K2_BH + doff, g_cat_hi + so);
        cp16(base + K2_BL + doff, g_cat_lo + so);
    }
}

// one K=64 chunk: fused 3-term inner loop (frags loaded once per k-step)
__device__ __forceinline__ void k2_gemm(float acc[2][8][4], const unsigned char* sm,
                                        int stage, int m0, int n0, int r, int c) {
    const __nv_bfloat16* AH = (const __nv_bfloat16*)(sm + stage * K2_STAGE + K2_AH);
    const __nv_bfloat16* AL = (const __nv_bfloat16*)(sm + stage * K2_STAGE + K2_AL);
    const __nv_bfloat16* BH = (const __nv_bfloat16*)(sm + stage * K2_STAGE + K2_BH);
    const __nv_bfloat16* BL = (const __nv_bfloat16*)(sm + stage * K2_STAGE + K2_BL);
    #pragma unroll
    for (int kk = 0; kk < 4; kk++) {
        const int k0 = kk * 16;
        uint32_t aH[2][4], aL[2][4];
        #pragma unroll
        for (int mi = 0; mi < 2; mi++) {
            const __nv_bfloat16* pH = AH + (m0 + mi*16 + r)*SK + k0 + c;
            const __nv_bfloat16* pL = AL + (m0 + mi*16 + r)*SK + k0 + c;
            aH[mi][0] = *(const uint32_t*)pH;
            aH[mi][1] = *(const uint32_t*)(pH + 8*SK);
            aH[mi][2] = *(const uint32_t*)(pH + 8);
            aH[mi][3] = *(const uint32_t*)(pH + 8*SK + 8);
            aL[mi][0] = *(const uint32_t*)pL;
            aL[mi][1] = *(const uint32_t*)(pL + 8*SK);
            aL[mi][2] = *(const uint32_t*)(pL + 8);
            aL[mi][3] = *(const uint32_t*)(pL + 8*SK + 8);
        }
        #pragma unroll
        for (int ni = 0; ni < 8; ni++) {
            const __nv_bfloat16* pH = BH + (n0 + ni*8 + r)*SK + k0 + c;
            const __nv_bfloat16* pL = BL + (n0 + ni*8 + r)*SK + k0 + c;
            uint32_t bH[2], bL[2];
            bH[0] = *(const uint32_t*)pH; bH[1] = *(const uint32_t*)(pH + 8);
            bL[0] = *(const uint32_t*)pL; bL[1] = *(const uint32_t*)(pL + 8);
            #pragma unroll
            for (int mi = 0; mi < 2; mi++) {
                mma_bf16(acc[mi][ni], aH[mi], bH);
                mma_bf16(acc[mi][ni], aH[mi], bL);
                mma_bf16(acc[mi][ni], aL[mi], bH);
            }
        }
    }
}

__global__ __launch_bounds__(512, 1)
void k2(const float* __restrict__ b2v, float* __restrict__ out)
{
    extern __shared__ unsigned char sm[];
    const uint32_t sbu = s2u(sm);
    const int tid = threadIdx.x, lane = tid & 31, wid = tid >> 5;
    const int r = lane >> 2, c = (lane & 3) * 2;
    const int m0 = (wid >> 1) * 32, n0 = (wid & 1) * 64;
    const int col0 = blockIdx.x * 128;

    float acc[2][8][4];
    #pragma unroll
    for (int i = 0; i < 2; i++)
        #pragma unroll
        for (int j = 0; j < 8; j++)
            #pragma unroll
            for (int v = 0; v < 4; v++) acc[i][j][v] = 0.f;

    k2_load(sm, sbu, 0, 0, col0, tid); CP_COMMIT();
    // ks = 0
    k2_load(sm, sbu, 1, 1, col0, tid); CP_COMMIT();
    CP_WAIT(1); __syncthreads();
    k2_gemm(acc, sm, 0, m0, n0, r, c); __syncthreads();
    // ks = 1
    k2_load(sm, sbu, 0, 2, col0, tid); CP_COMMIT();
    CP_WAIT(1); __syncthreads();
    k2_gemm(acc, sm, 1, m0, n0, r, c); __syncthreads();
    // ks = 2
    k2_load(sm, sbu, 1, 3, col0, tid); CP_COMMIT();
    CP_WAIT(1); __syncthreads();
    k2_gemm(acc, sm, 0, m0, n0, r, c); __syncthreads();
    // ks = 3
    CP_WAIT(0); __syncthreads();
    k2_gemm(acc, sm, 1, m0, n0, r, c);

    // Epilogue: bias + relu + direct store, out[b][d][node]
    #pragma unroll
    for (int mi = 0; mi < 2; mi++) {
        int mr = m0 + mi*16 + r;
        float bias_a = b2v[mr], bias_b = b2v[mr + 8];
        #pragma unroll
        for (int ni = 0; ni < 8; ni++) {
            int nc = n0 + ni*8 + c;
            int colA = col0 + nc, colB = colA + 1;
            int ba = colA / Nn, bb = colB / Nn;
            size_t obA = (size_t)ba * CO * Nn + (colA - ba * Nn);
            size_t obB = (size_t)bb * CO * Nn + (colB - bb * Nn);
            out[obA + (size_t)mr * Nn]     = fmaxf(acc[mi][ni][0] + bias_a, 0.f);
            out[obB + (size_t)mr * Nn]     = fmaxf(acc[mi][ni][1] + bias_a, 0.f);
            out[obA + (size_t)(mr+8) * Nn] = fmaxf(acc[mi][ni][2] + bias_b, 0.f);
            out[obB + (size_t)(mr+8) * Nn] = fmaxf(acc[mi][ni][3] + bias_b, 0.f);
        }
    }
}

// ---------------------------------------------------------------------------
extern "C" void kernel_launch(void* const* d_in, const int* in_sizes, int n_in,
                              void* d_out, int out_size)
{
    const float* x  = (const float*)d_in[0];
    const int*   ei = (const int*)  d_in[1];
    const float* W1 = (const float*)d_in[2];
    const float* b1 = (const float*)d_in[3];
    const float* Wp = (const float*)d_in[4];
    const float* bp = (const float*)d_in[5];
    const float* W2 = (const float*)d_in[6];
    const float* b2 = (const float*)d_in[7];
    float* out = (float*)d_out;

    const int s1 = 139776;
    const int s2 = 2 * K2_STAGE;      // 221184
    cudaFuncSetAttribute(k1, cudaFuncAttributeMaxDynamicSharedMemorySize, s1);
    cudaFuncSetAttribute(k2, cudaFuncAttributeMaxDynamicSharedMemorySize, s2);

    kw<<<384, 256>>>(W1, Wp, W2);
    k1<<<NT / 128, 256, s1>>>(x, b1, bp);
    kg<<<NT / 8, 256>>>(ei);
    k2<<<NT / 128, 512, s2>>>(b2, out);
}

// round 7
// speedup vs baseline: 2.7953x; 1.0012x over previous
#include <cuda_runtime.h>
#include <cuda_bf16.h>
#include <cstdint>

#define Bb 8
#define Cc 128
#define Nn 10000
#define Kk 16
#define CO 256
#define NT (Bb*Nn)
#define S1 136              // k1 padded smem stride (elements)
#define SK 72               // k2 chunk stride (64 k-elems + 8 pad)

// ---------------------------------------------------------------------------
// Device scratch
// ---------------------------------------------------------------------------
// [W1hi 16384][W1lo 16384][Wphi 16384][Wplo 16384][W2hi 65536][W2lo 65536]
__device__ __align__(16) __nv_bfloat16 g_wimg[4*16384 + 2*65536];
__device__ __align__(16) __nv_bfloat16 g_cat_hi[(size_t)NT*128];   // h only
__device__ __align__(16) __nv_bfloat16 g_cat_lo[(size_t)NT*128];
__device__ __align__(16) float g_q[(size_t)NT*128];

__device__ __forceinline__ void split_bf16(float v, __nv_bfloat16& h, __nv_bfloat16& l) {
    h = __float2bfloat16(v);
    l = __float2bfloat16(v - __bfloat162float(h));
}
__device__ __forceinline__ uint32_t packbf(__nv_bfloat16 a, __nv_bfloat16 b) {
    __nv_bfloat162 p{a, b};
    return *(uint32_t*)&p;
}

// D(16x8,f32) += A(16x16,bf16 row) * B(16x8,bf16 col)
__device__ __forceinline__ void mma_bf16(float* d, const uint32_t* a, const uint32_t* b) {
    asm("mma.sync.aligned.m16n8k16.row.col.f32.bf16.bf16.f32 "
        "{%0,%1,%2,%3}, {%4,%5,%6,%7}, {%8,%9}, {%0,%1,%2,%3};"
        : "+f"(d[0]), "+f"(d[1]), "+f"(d[2]), "+f"(d[3])
        : "r"(a[0]), "r"(a[1]), "r"(a[2]), "r"(a[3]), "r"(b[0]), "r"(b[1]));
}

__device__ __forceinline__ uint32_t s2u(const void* p) {
    uint32_t a;
    asm("{ .reg .u64 t; cvta.to.shared.u64 t, %1; cvt.u32.u64 %0, t; }" : "=r"(a) : "l"(p));
    return a;
}
__device__ __forceinline__ void cp16(uint32_t dst, const void* src) {
    asm volatile("cp.async.cg.shared.global [%0], [%1], 16;" :: "r"(dst), "l"(src));
}
#define CP_COMMIT() asm volatile("cp.async.commit_group;" ::: "memory")
#define CP_WAIT(N)  asm volatile("cp.async.wait_group %0;" :: "n"(N) : "memory")

// Warp GEMM, tile 32(M) x 32(N), K=128, 3-term hi/lo split (k1, stride S1).
__device__ __forceinline__ void gemm_2x4(float acc[2][4][4],
        const __nv_bfloat16* WH, const __nv_bfloat16* WL,
        const __nv_bfloat16* BH, const __nv_bfloat16* BL,
        int m0, int n0, int r, int c)
{
    #pragma unroll
    for (int kk = 0; kk < 8; kk++) {
        const int k0 = kk * 16;
        uint32_t aH[2][4], aL[2][4];
        #pragma unroll
        for (int mi = 0; mi < 2; mi++) {
            const __nv_bfloat16* pH = WH + (m0 + mi*16 + r)*S1 + k0 + c;
            const __nv_bfloat16* pL = WL + (m0 + mi*16 + r)*S1 + k0 + c;
            aH[mi][0] = *(const uint32_t*)pH;
            aH[mi][1] = *(const uint32_t*)(pH + 8*S1);
            aH[mi][2] = *(const uint32_t*)(pH + 8);
            aH[mi][3] = *(const uint32_t*)(pH + 8*S1 + 8);
            aL[mi][0] = *(const uint32_t*)pL;
            aL[mi][1] = *(const uint32_t*)(pL + 8*S1);
            aL[mi][2] = *(const uint32_t*)(pL + 8);
            aL[mi][3] = *(const uint32_t*)(pL + 8*S1 + 8);
        }
        #pragma unroll
        for (int ni = 0; ni < 4; ni++) {
            const __nv_bfloat16* pH = BH + (n0 + ni*8 + r)*S1 + k0 + c;
            const __nv_bfloat16* pL = BL + (n0 + ni*8 + r)*S1 + k0 + c;
            uint32_t bH[2], bL[2];
            bH[0] = *(const uint32_t*)pH; bH[1] = *(const uint32_t*)(pH + 8);
            bL[0] = *(const uint32_t*)pL; bL[1] = *(const uint32_t*)(pL + 8);
            #pragma unroll
            for (int mi = 0; mi < 2; mi++) {
                mma_bf16(acc[mi][ni], aH[mi], bH);
                mma_bf16(acc[mi][ni], aH[mi], bL);
                mma_bf16(acc[mi][ni], aL[mi], bH);
            }
        }
    }
}

// ---------------------------------------------------------------------------
// kw: one-time split of weights into bf16 hi/lo global images
// ---------------------------------------------------------------------------
__global__ void kw(const float* __restrict__ W1, const float* __restrict__ Wp,
                   const float* __restrict__ W2) {
    int t = blockIdx.x * 256 + threadIdx.x;     // 98304
    __nv_bfloat16 h, l;
    if (t < 16384) {
        split_bf16(W1[t], h, l);
        g_wimg[t] = h; g_wimg[16384 + t] = l;
    } else if (t < 32768) {
        int e = t - 16384;
        split_bf16(Wp[e], h, l);
        g_wimg[32768 + e] = h; g_wimg[49152 + e] = l;
    } else {
        int e = t - 32768;
        split_bf16(W2[e], h, l);
        g_wimg[65536 + e] = h; g_wimg[131072 + e] = l;
    }
}

// ---------------------------------------------------------------------------
// k1: per 128-node tile: h = relu(W1@x+b1); q = relu(Wp@h+bp)
//     h -> g_cat (bf16 hi/lo), q -> g_q (fp32). 512 threads, 16 warps.
// ---------------------------------------------------------------------------
__global__ __launch_bounds__(512, 1)
void k1(const float* __restrict__ x, const float* __restrict__ b1v,
        const float* __restrict__ bpv)
{
    extern __shared__ unsigned char sm[];
    int* xb = (int*)sm;
    __nv_bfloat16* WH = (__nv_bfloat16*)(sm + 512);
    __nv_bfloat16* WL = WH + 128*S1;
    __nv_bfloat16* BH = (__nv_bfloat16*)(sm + 512 + 69632);
    __nv_bfloat16* BL = BH + 128*S1;
    float* Q = (float*)BH;                 // overlay after GEMM2 (stride 132)

    const int tid = threadIdx.x, lane = tid & 31, wid = tid >> 5;
    const int r = lane >> 2, c = (lane & 3) * 2;
    const int m0 = (wid >> 2) * 32, n0 = (wid & 3) * 32;
    const int col0 = blockIdx.x * 128;

    if (tid < 128) {
        int col = col0 + tid, b = col / Nn;
        xb[tid] = b * (Cc * Nn) + (col - b * Nn);
    }
    {   // W1 hi/lo -> smem
        const uint32_t* sH = (const uint32_t*)g_wimg;
        const uint32_t* sL = sH + 8192;
        uint32_t* dH = (uint32_t*)WH;
        uint32_t* dL = (uint32_t*)WL;
        #pragma unroll 4
        for (int i = tid; i < 8192; i += 512) {
            int m = i >> 6, w = i & 63;
            dH[m*68 + w] = sH[i];
            dL[m*68 + w] = sL[i];
        }
    }
    __syncthreads();

    // x tile -> B planes (node-major, split)
    for (int i = tid; i < 16384; i += 512) {
        int j = i & 127, ch = i >> 7;
        float v = x[xb[j] + ch * Nn];
        __nv_bfloat16 h, l; split_bf16(v, h, l);
        BH[j*S1 + ch] = h;
        BL[j*S1 + ch] = l;
    }
    __syncthreads();

    float acc[2][4][4];
    #pragma unroll
    for (int i = 0; i < 2; i++)
        #pragma unroll
        for (int j = 0; j < 4; j++)
            #pragma unroll
            for (int v = 0; v < 4; v++) acc[i][j][v] = 0.f;

    gemm_2x4(acc, WH, WL, BH, BL, m0, n0, r, c);
    __syncthreads();

    // Epilogue 1: h -> B planes ; Wp -> WA
    #pragma unroll
    for (int mi = 0; mi < 2; mi++) {
        int mr = m0 + mi*16 + r;
        float bias_a = b1v[mr], bias_b = b1v[mr + 8];
        #pragma unroll
        for (int ni = 0; ni < 4; ni++) {
            int nc = n0 + ni*8 + c;
            __nv_bfloat16 h, l;
            float v;
            v = fmaxf(acc[mi][ni][0] + bias_a, 0.f); split_bf16(v, h, l);
            BH[nc*S1 + mr] = h;       BL[nc*S1 + mr] = l;
            v = fmaxf(acc[mi][ni][1] + bias_a, 0.f); split_bf16(v, h, l);
            BH[(nc+1)*S1 + mr] = h;   BL[(nc+1)*S1 + mr] = l;
            v = fmaxf(acc[mi][ni][2] + bias_b, 0.f); split_bf16(v, h, l);
            BH[nc*S1 + mr+8] = h;     BL[nc*S1 + mr+8] = l;
            v = fmaxf(acc[mi][ni][3] + bias_b, 0.f); split_bf16(v, h, l);
            BH[(nc+1)*S1 + mr+8] = h; BL[(nc+1)*S1 + mr+8] = l;
        }
    }
    {   // Wp hi/lo -> WA
        const uint32_t* sH = (const uint32_t*)(g_wimg + 32768);
        const uint32_t* sL = (const uint32_t*)(g_wimg + 49152);
        uint32_t* dH = (uint32_t*)WH;
        uint32_t* dL = (uint32_t*)WL;
        #pragma unroll 4
        for (int i = tid; i < 8192; i += 512) {
            int m = i >> 6, w = i & 63;
            dH[m*68 + w] = sH[i];
            dL[m*68 + w] = sL[i];
        }
    }
    __syncthreads();

    // h rows -> g_cat (coalesced uint4)
    for (int i = tid; i < 2048; i += 512) {
        int j = i >> 4, v = i & 15;
        ((uint4*)(g_cat_hi + (size_t)(col0 + j) * 128))[v] = ((const uint4*)(BH + j*S1))[v];
        ((uint4*)(g_cat_lo + (size_t)(col0 + j) * 128))[v] = ((const uint4*)(BL + j*S1))[v];
    }

    #pragma unroll
    for (int i = 0; i < 2; i++)
        #pragma unroll
        for (int j = 0; j < 4; j++)
            #pragma unroll
            for (int v = 0; v < 4; v++) acc[i][j][v] = 0.f;

    gemm_2x4(acc, WH, WL, BH, BL, m0, n0, r, c);
    __syncthreads();

    // Epilogue 2: q -> staging (fp32, stride 132)
    #pragma unroll
    for (int mi = 0; mi < 2; mi++) {
        int mr = m0 + mi*16 + r;
        float bias_a = bpv[mr], bias_b = bpv[mr + 8];
        #pragma unroll
        for (int ni = 0; ni < 4; ni++) {
            int nc = n0 + ni*8 + c;
            Q[nc*132 + mr]       = fmaxf(acc[mi][ni][0] + bias_a, 0.f);
            Q[(nc+1)*132 + mr]   = fmaxf(acc[mi][ni][1] + bias_a, 0.f);
            Q[nc*132 + mr+8]     = fmaxf(acc[mi][ni][2] + bias_b, 0.f);
            Q[(nc+1)*132 + mr+8] = fmaxf(acc[mi][ni][3] + bias_b, 0.f);
        }
    }
    __syncthreads();

    for (int i = tid; i < 4096; i += 512) {
        int j = i >> 5, v = i & 31;
        ((float4*)(g_q + (size_t)(col0 + j) * 128))[v] = ((const float4*)(Q + j*132))[v];
    }
}

// ---------------------------------------------------------------------------
// k2: out = relu(W2 @ cat + b2). M=256, N=128/block. K=256 in 4 chunks of 64,
//     double-buffered cp.async; chunks 2,3 B operand GATHERED in-kernel from g_q.
// ---------------------------------------------------------------------------
#define K2_STAGE 110592
#define K2_AH 0
#define K2_AL 36864
#define K2_BH 73728
#define K2_BL 92160

__device__ __forceinline__ void k2_load_a(uint32_t sbu, int stage, int ks, int tid) {
    const uint32_t base = sbu + stage * K2_STAGE;
    const __nv_bfloat16* srcH = g_wimg + 65536;
    const __nv_bfloat16* srcL = g_wimg + 131072;
    #pragma unroll
    for (int t = 0; t < 4; t++) {
        int i = tid + t * 512;           // 0..2047
        int m = i >> 3, ch = i & 7;
        int so = m * 256 + ks * 64 + ch * 8;
        uint32_t doff = (uint32_t)(m * SK + ch * 8) * 2;
        cp16(base + K2_AH + doff, srcH + so);
        cp16(base + K2_AL + doff, srcL + so);
    }
}
__device__ __forceinline__ void k2_load_b_cat(uint32_t sbu, int stage, int ks,
                                              int col0, int tid) {
    const uint32_t base = sbu + stage * K2_STAGE;
    #pragma unroll
    for (int t = 0; t < 2; t++) {
        int i = tid + t * 512;           // 0..1023
        int j = i >> 3, ch = i & 7;
        size_t so = (size_t)(col0 + j) * 128 + ks * 64 + ch * 8;
        uint32_t doff = (uint32_t)(j * SK + ch * 8) * 2;
        cp16(base + K2_BH + doff, g_cat_hi + so);
        cp16(base + K2_BL + doff, g_cat_lo + so);
    }
}

// gather-max 128 nodes x 128 ch into packed bf16 hi/lo regs.
// Round t: warp handles node j = wid + 16*t; lane covers ch = lane*4 (float4).
__device__ __forceinline__ void k2_gather(const int* __restrict__ eidx, int col0,
                                          int wid, int lane,
                                          uint32_t gh[8][2], uint32_t gl[8][2]) {
    #pragma unroll
    for (int t = 0; t < 8; t++) {
        int col = col0 + wid + 16 * t;
        int b = col / Nn;
        const float* qb = g_q + (size_t)b * Nn * 128;
        int id = 0;
        if (lane < Kk) id = eidx[col * Kk + lane];
        float4 m = make_float4(0.f, 0.f, 0.f, 0.f);   // relu output >= 0
        #pragma unroll
        for (int k = 0; k < Kk; k++) {
            int nb = __shfl_sync(0xffffffffu, id, k);
            float4 v = ((const float4*)(qb + (size_t)nb * 128))[lane];
            m.x = fmaxf(m.x, v.x); m.y = fmaxf(m.y, v.y);
            m.z = fmaxf(m.z, v.z); m.w = fmaxf(m.w, v.w);
        }
        __nv_bfloat16 h0,l0,h1,l1,h2,l2,h3,l3;
        split_bf16(m.x, h0, l0); split_bf16(m.y, h1, l1);
        split_bf16(m.z, h2, l2); split_bf16(m.w, h3, l3);
        gh[t][0] = packbf(h0, h1); gh[t][1] = packbf(h2, h3);
        gl[t][0] = packbf(l0, l1); gl[t][1] = packbf(l2, l3);
    }
}

// lanes 0-15 hold chunk2 (half=0), lanes 16-31 chunk3 (half=1)
__device__ __forceinline__ void k2_store_gather(unsigned char* sm, int stage, int half,
                                                const uint32_t gh[8][2],
                                                const uint32_t gl[8][2],
                                                int wid, int lane) {
    if ((lane >> 4) != half) return;
    const int kloc = (lane & 15) * 4;
    unsigned char* BH = sm + stage * K2_STAGE + K2_BH;
    unsigned char* BL = sm + stage * K2_STAGE + K2_BL;
    #pragma unroll
    for (int t = 0; t < 8; t++) {
        int j = wid + 16 * t;
        *(uint2*)(BH + (j * SK + kloc) * 2) = make_uint2(gh[t][0], gh[t][1]);
        *(uint2*)(BL + (j * SK + kloc) * 2) = make_uint2(gl[t][0], gl[t][1]);
    }
}

__device__ __forceinline__ void k2_gemm(float acc[2][8][4], const unsigned char* sm,
                                        int stage, int m0, int n0, int r, int c) {
    const __nv_bfloat16* AH = (const __nv_bfloat16*)(sm + stage * K2_STAGE + K2_AH);
    const __nv_bfloat16* AL = (const __nv_bfloat16*)(sm + stage * K2_STAGE + K2_AL);
    const __nv_bfloat16* BH = (const __nv_bfloat16*)(sm + stage * K2_STAGE + K2_BH);
    const __nv_bfloat16* BL = (const __nv_bfloat16*)(sm + stage * K2_STAGE + K2_BL);
    #pragma unroll
    for (int kk = 0; kk < 4; kk++) {
        const int k0 = kk * 16;
        uint32_t aH[2][4], aL[2][4];
        #pragma unroll
        for (int mi = 0; mi < 2; mi++) {
            const __nv_bfloat16* pH = AH + (m0 + mi*16 + r)*SK + k0 + c;
            const __nv_bfloat16* pL = AL + (m0 + mi*16 + r)*SK + k0 + c;
            aH[mi][0] = *(const uint32_t*)pH;
            aH[mi][1] = *(const uint32_t*)(pH + 8*SK);
            aH[mi][2] = *(const uint32_t*)(pH + 8);
            aH[mi][3] = *(const uint32_t*)(pH + 8*SK + 8);
            aL[mi][0] = *(const uint32_t*)pL;
            aL[mi][1] = *(const uint32_t*)(pL + 8*SK);
            aL[mi][2] = *(const uint32_t*)(pL + 8);
            aL[mi][3] = *(const uint32_t*)(pL + 8*SK + 8);
        }
        #pragma unroll
        for (int ni = 0; ni < 8; ni++) {
            const __nv_bfloat16* pH = BH + (n0 + ni*8 + r)*SK + k0 + c;
            const __nv_bfloat16* pL = BL + (n0 + ni*8 + r)*SK + k0 + c;
            uint32_t bH[2], bL[2];
            bH[0] = *(const uint32_t*)pH; bH[1] = *(const uint32_t*)(pH + 8);
            bL[0] = *(const uint32_t*)pL; bL[1] = *(const uint32_t*)(pL + 8);
            #pragma unroll
            for (int mi = 0; mi < 2; mi++) {
                mma_bf16(acc[mi][ni], aH[mi], bH);
                mma_bf16(acc[mi][ni], aH[mi], bL);
                mma_bf16(acc[mi][ni], aL[mi], bH);
            }
        }
    }
}

__global__ __launch_bounds__(512)
void k2(const int* __restrict__ eidx, const float* __restrict__ b2v,
        float* __restrict__ out)
{
    extern __shared__ unsigned char sm[];
    const uint32_t sbu = s2u(sm);
    const int tid = threadIdx.x, lane = tid & 31, wid = tid >> 5;
    const int r = lane >> 2, c = (lane & 3) * 2;
    const int m0 = (wid >> 1) * 32, n0 = (wid & 1) * 64;
    const int col0 = blockIdx.x * 128;

    // Prefetch chunks 0,1 (A = W2 slices; B = h from g_cat)
    k2_load_a(sbu, 0, 0, tid); k2_load_b_cat(sbu, 0, 0, col0, tid); CP_COMMIT(); // G0
    k2_load_a(sbu, 1, 1, tid); k2_load_b_cat(sbu, 1, 1, col0, tid); CP_COMMIT(); // G1

    // Gather chunks 2,3 into registers (overlaps G0/G1 arrival)
    uint32_t gh[8][2], gl[8][2];
    k2_gather(eidx, col0, wid, lane, gh, gl);

    float acc[2][8][4];
    #pragma unroll
    for (int i = 0; i < 2; i++)
        #pragma unroll
        for (int j = 0; j < 8; j++)
            #pragma unroll
            for (int v = 0; v < 4; v++) acc[i][j][v] = 0.f;

    CP_WAIT(1); __syncthreads();           // G0 done
    k2_gemm(acc, sm, 0, m0, n0, r, c);     // chunk 0
    __syncthreads();                       // stage0 B free

    k2_store_gather(sm, 0, 0, gh, gl, wid, lane);   // chunk2 -> B(st0)
    k2_load_a(sbu, 0, 2, tid); CP_COMMIT();          // G2 (A only)
    CP_WAIT(1); __syncthreads();           // G1 done
    k2_gemm(acc, sm, 1, m0, n0, r, c);     // chunk 1
    __syncthreads();                       // stage1 B free

    k2_store_gather(sm, 1, 1, gh, gl, wid, lane);   // chunk3 -> B(st1)
    k2_load_a(sbu, 1, 3, tid); CP_COMMIT();          // G3
    CP_WAIT(1); __syncthreads();           // G2 done (+ STS visible)
    k2_gemm(acc, sm, 0, m0, n0, r, c);     // chunk 2
    __syncthreads();
    CP_WAIT(0); __syncthreads();           // G3 done
    k2_gemm(acc, sm, 1, m0, n0, r, c);     // chunk 3

    // Epilogue: bias + relu + direct store, out[b][d][node]
    #pragma unroll
    for (int mi = 0; mi < 2; mi++) {
        int mr = m0 + mi*16 + r;
        float bias_a = b2v[mr], bias_b = b2v[mr + 8];
        #pragma unroll
        for (int ni = 0; ni < 8; ni++) {
            int nc = n0 + ni*8 + c;
            int colA = col0 + nc, colB = colA + 1;
            int ba = colA / Nn, bb = colB / Nn;
            size_t obA = (size_t)ba * CO * Nn + (colA - ba * Nn);
            size_t obB = (size_t)bb * CO * Nn + (colB - bb * Nn);
            out[obA + (size_t)mr * Nn]     = fmaxf(acc[mi][ni][0] + bias_a, 0.f);
            out[obB + (size_t)mr * Nn]     = fmaxf(acc[mi][ni][1] + bias_a, 0.f);
            out[obA + (size_t)(mr+8) * Nn] = fmaxf(acc[mi][ni][2] + bias_b, 0.f);
            out[obB + (size_t)(mr+8) * Nn] = fmaxf(acc[mi][ni][3] + bias_b, 0.f);
        }
    }
}

// ---------------------------------------------------------------------------
extern "C" void kernel_launch(void* const* d_in, const int* in_sizes, int n_in,
                              void* d_out, int out_size)
{
    const float* x  = (const float*)d_in[0];
    const int*   ei = (const int*)  d_in[1];
    const float* W1 = (const float*)d_in[2];
    const float* b1 = (const float*)d_in[3];
    const float* Wp = (const float*)d_in[4];
    const float* bp = (const float*)d_in[5];
    const float* W2 = (const float*)d_in[6];
    const float* b2 = (const float*)d_in[7];
    float* out = (float*)d_out;

    const int s1 = 139776;
    const int s2 = 2 * K2_STAGE;      // 221184
    cudaFuncSetAttribute(k1, cudaFuncAttributeMaxDynamicSharedMemorySize, s1);
    cudaFuncSetAttribute(k2, cudaFuncAttributeMaxDynamicSharedMemorySize, s2);

    kw<<<384, 256>>>(W1, Wp, W2);
    k1<<<NT / 128, 512, s1>>>(x, b1, bp);
    k2<<<NT / 128, 512, s2>>>(ei, b2, out);
}